// round 15
// baseline (speedup 1.0000x reference)
#include <cuda_runtime.h>
#include <cuda_bf16.h>
#include <stdint.h>

#define BB 4
#define TT 4096
#define DD 1024
#define DH 64
#define NROW (BB*TT)
#define QT 32
#define CKT 8
#define NCHUNK 4
#define SCALE 0.03125f

#define SWZ(o) ((o) ^ (((o) >> 3) & 0x70))

__device__ __forceinline__ uint32_t s2u(const void* p) {
    uint32_t a; asm("{ .reg .u64 t; cvta.to.shared.u64 t, %1; cvt.u32.u64 %0, t; }" : "=r"(a) : "l"(p)); return a;
}
__device__ __forceinline__ uint32_t swaddr(uint32_t base, int row, int cb) {
    uint32_t o = (uint32_t)(row * 128 + cb);
    return base + (o ^ ((o >> 3) & 0x70));
}
__device__ __forceinline__ void ldsm4(uint32_t& r0, uint32_t& r1, uint32_t& r2, uint32_t& r3, uint32_t a) {
    asm volatile("ldmatrix.sync.aligned.m8n8.x4.shared.b16 {%0,%1,%2,%3}, [%4];"
                 : "=r"(r0), "=r"(r1), "=r"(r2), "=r"(r3) : "r"(a));
}
__device__ __forceinline__ void ldsm4t(uint32_t& r0, uint32_t& r1, uint32_t& r2, uint32_t& r3, uint32_t a) {
    asm volatile("ldmatrix.sync.aligned.m8n8.x4.trans.shared.b16 {%0,%1,%2,%3}, [%4];"
                 : "=r"(r0), "=r"(r1), "=r"(r2), "=r"(r3) : "r"(a));
}
__device__ __forceinline__ void mma16816(float* c, const uint32_t* a, uint32_t b0, uint32_t b1) {
    asm volatile("mma.sync.aligned.m16n8k16.row.col.f32.bf16.bf16.f32 "
                 "{%0,%1,%2,%3}, {%4,%5,%6,%7}, {%8,%9}, {%0,%1,%2,%3};"
                 : "+f"(c[0]), "+f"(c[1]), "+f"(c[2]), "+f"(c[3])
                 : "r"(a[0]), "r"(a[1]), "r"(a[2]), "r"(a[3]), "r"(b0), "r"(b1));
}
// cp.async 16B (sm_80 baseline PTX; LDGSTS in SASS)
__device__ __forceinline__ void cp16(uint32_t dst, const void* src) {
    uint64_t g; asm("cvta.to.global.u64 %0, %1;" : "=l"(g) : "l"(src));
    asm volatile("cp.async.cg.shared.global [%0], [%1], 16;" :: "r"(dst), "l"(g));
}
#define CPCOMMIT() asm volatile("cp.async.commit_group;" ::: "memory")
#define CPWAIT(n)  asm volatile("cp.async.wait_group %0;" :: "n"(n) : "memory")

__device__ __forceinline__ void splitpk(float f0, float f1, uint32_t& h, uint32_t& l) {
    __nv_bfloat162 hb = __floats2bfloat162_rn(f0, f1);
    h = *(uint32_t*)&hb;
    float l0 = f0 - __bfloat162float(hb.x);
    float l1 = f1 - __bfloat162float(hb.y);
    __nv_bfloat162 lb = __floats2bfloat162_rn(l0, l1);
    l = *(uint32_t*)&lb;
}
__device__ __forceinline__ uint32_t pk2bf(float f0, float f1) {
    __nv_bfloat162 hb = __floats2bfloat162_rn(f0, f1);
    return *(uint32_t*)&hb;
}

// ---------------- device scratch ----------------
__device__ __nv_bfloat16 g_Wth[3*DH*DD];          // [mat][n][k]
__device__ __nv_bfloat16 g_Wtl[3*DH*DD];
__device__ __nv_bfloat16 g_Qh[(long)NROW*DH];     // Q: single bf16 (damped via S)
__device__ __nv_bfloat16 g_Kh[(long)NROW*DH];     // K: single bf16 (damped via S)
__device__ __nv_bfloat16 g_Vh[(long)NROW*DH], g_Vl[(long)NROW*DH];  // V: hi/lo (undamped)
__device__ float g_Vsum[(NROW/128)*64];           // per key tile: column sums of V (fp32)
__device__ float g_Op[(long)BB*QT*NCHUNK*128*DH];
__device__ float g_lp[BB*QT*NCHUNK*128];

// ================= Kernel 0: W transpose + hi/lo split =================
__global__ void wprep_kernel(const float* __restrict__ Wq,
                             const float* __restrict__ Wk,
                             const float* __restrict__ Wv) {
    __shared__ float Ws[128*65];
    int mat = blockIdx.x >> 3;
    int k0  = (blockIdx.x & 7) * 128;
    const float* W = (mat == 0) ? Wq : (mat == 1) ? Wk : Wv;
    int tid = threadIdx.x;
    for (int i = tid; i < 2048; i += 256) {
        int k = i >> 4, n4 = (i & 15) * 4;
        float4 w = *(const float4*)&W[(long)(k0 + k)*DH + n4];
        float* p = &Ws[k*65 + n4];
        p[0] = w.x; p[1] = w.y; p[2] = w.z; p[3] = w.w;
    }
    __syncthreads();
    for (int i = tid; i < 2048; i += 256) {
        int n = i >> 5, k4 = (i & 31) * 4;
        uint32_t h0, l0, h1, l1;
        splitpk(Ws[(k4+0)*65 + n], Ws[(k4+1)*65 + n], h0, l0);
        splitpk(Ws[(k4+2)*65 + n], Ws[(k4+3)*65 + n], h1, l1);
        long off = (long)mat*DH*DD + (long)n*DD + k0 + k4;
        *(uint2*)&g_Wth[off] = make_uint2(h0, h1);
        *(uint2*)&g_Wtl[off] = make_uint2(l0, l1);
    }
}

// ================= Kernel 1: QKV projection via mma.sync (pipelined) =================
// Terms: Q,K = Xh*Wh (1, damped via S);  V = Xh*Wh + Xh*Wl + Xl*Wh (3, undamped).
#define PB 81920
#define PJ_XS 0
#define PJ_WB 32768
#define PJ_XHs (2*PB)
#define PJ_XLs (2*PB + 16384)
#define PROJ_SMEM (2*PB + 32768)

__device__ __forceinline__ void proj_prefetch(uint32_t sb, char* smem, int p,
                                              const float* x, long rowbase, int k0, int tid) {
    uint32_t base = sb + p*PB;
    for (int i = tid; i < 2048; i += 256) {
        int r = i >> 4, c4 = (i & 15) * 4;
        cp16(base + PJ_XS + (uint32_t)(r*256 + c4*4), &x[(rowbase + r)*DD + k0 + c4]);
    }
    // W tiles needed: t in {0 (Q-hi), 2 (K-hi), 4 (V-hi), 5 (V-lo)}
    for (int i = tid; i < 2048; i += 256) {
        int tt = i >> 9, idx = i & 511;
        int t = (tt == 0) ? 0 : (tt == 1) ? 2 : tt + 2;
        int n = idx >> 3, k8 = (idx & 7) * 8;
        int mat = t >> 1, hl = t & 1;
        const __nv_bfloat16* src = (hl ? g_Wtl : g_Wth) + (long)mat*DH*DD;
        cp16(base + PJ_WB + t*8192 + SWZ((uint32_t)(n*128 + k8*2)), &src[(long)n*DD + k0 + k8]);
    }
}

__global__ void __launch_bounds__(256, 1) proj_kernel(const float* __restrict__ x) {
    extern __shared__ char smem[];
    uint32_t sb = s2u(smem);
    int tid = threadIdx.x, lane = tid & 31, w = tid >> 5;
    long rowbase = (long)blockIdx.x * 128;

    float c[24][4];
    #pragma unroll
    for (int i = 0; i < 24; i++)
        #pragma unroll
        for (int k = 0; k < 4; k++) c[i][k] = 0.f;

    proj_prefetch(sb, smem, 0, x, rowbase, 0, tid);
    CPCOMMIT();

    for (int kc = 0; kc < 16; kc++) {
        int p = kc & 1;
        __syncthreads();
        if (kc + 1 < 16) {
            proj_prefetch(sb, smem, (kc+1) & 1, x, rowbase, (kc+1)*64, tid);
            CPCOMMIT();
            CPWAIT(1);
        } else {
            CPWAIT(0);
        }
        __syncthreads();
        {
            const float* xs = (const float*)(smem + p*PB + PJ_XS);
            for (int i = tid; i < 2048; i += 256) {
                int r = i >> 4, c4 = (i & 15) * 4;
                float4 v = *(const float4*)&xs[r*64 + c4];
                uint32_t h0, l0, h1, l1;
                splitpk(v.x, v.y, h0, l0);
                splitpk(v.z, v.w, h1, l1);
                uint32_t o = SWZ((uint32_t)(r*128 + c4*2));
                *(uint2*)(smem + PJ_XHs + o) = make_uint2(h0, h1);
                *(uint2*)(smem + PJ_XLs + o) = make_uint2(l0, l1);
            }
        }
        __syncthreads();
        uint32_t wbase = sb + p*PB + PJ_WB;
        #pragma unroll
        for (int ks = 0; ks < 4; ks++) {
            uint32_t ah[4], al[4];
            {
                int r = 16*w + (lane & 15);
                int cb = ks*32 + (lane >> 4) * 16;
                ldsm4(ah[0], ah[1], ah[2], ah[3], swaddr(sb + PJ_XHs, r, cb));
                ldsm4(al[0], al[1], al[2], al[3], swaddr(sb + PJ_XLs, r, cb));
            }
            #pragma unroll
            for (int mat = 0; mat < 3; mat++) {
                uint32_t bhB = wbase + (mat*2+0)*8192;
                uint32_t blB = wbase + (mat*2+1)*8192;
                #pragma unroll
                for (int j2 = 0; j2 < 4; j2++) {
                    uint32_t bh[4];
                    int r = j2*16 + ((lane >> 4) & 1)*8 + (lane & 7);
                    int cb = ks*32 + ((lane >> 3) & 1)*16;
                    ldsm4(bh[0], bh[1], bh[2], bh[3], swaddr(bhB, r, cb));
                    float* c0 = c[mat*8 + 2*j2];
                    float* c1 = c[mat*8 + 2*j2 + 1];
                    mma16816(c0, ah, bh[0], bh[1]);
                    mma16816(c1, ah, bh[2], bh[3]);
                    if (mat == 2) {
                        uint32_t bl[4];
                        ldsm4(bl[0], bl[1], bl[2], bl[3], swaddr(blB, r, cb));
                        mma16816(c0, al, bh[0], bh[1]);
                        mma16816(c1, al, bh[2], bh[3]);
                        mma16816(c0, ah, bl[0], bl[1]);
                        mma16816(c1, ah, bl[2], bl[3]);
                    }
                }
            }
        }
    }

    int g = lane >> 2, i2 = (lane & 3) * 2;

    // ---- V column sums for this 128-row tile (rank-1 flash correction) ----
    __syncthreads();
    {
        float* vss = (float*)(smem + PJ_XHs);   // [8 warps][64]
        float s0[8], s1[8];
        #pragma unroll
        for (int jt = 0; jt < 8; jt++) {
            s0[jt] = c[16+jt][0] + c[16+jt][2];
            s1[jt] = c[16+jt][1] + c[16+jt][3];
        }
        #pragma unroll
        for (int off = 4; off < 32; off <<= 1) {
            #pragma unroll
            for (int jt = 0; jt < 8; jt++) {
                s0[jt] += __shfl_xor_sync(0xffffffffu, s0[jt], off);
                s1[jt] += __shfl_xor_sync(0xffffffffu, s1[jt], off);
            }
        }
        if (lane < 4) {
            #pragma unroll
            for (int jt = 0; jt < 8; jt++) {
                vss[w*64 + 8*jt + i2]     = s0[jt];
                vss[w*64 + 8*jt + i2 + 1] = s1[jt];
            }
        }
        __syncthreads();
        if (tid < 64) {
            float t = 0.f;
            #pragma unroll
            for (int ww = 0; ww < 8; ww++) t += vss[ww*64 + tid];
            g_Vsum[(rowbase >> 7)*64 + tid] = t;
        }
    }

    // write Q,K (single bf16; Q scaled) and V (hi/lo)
    long r0 = rowbase + 16*w + g;
    long r1 = r0 + 8;
    #pragma unroll
    for (int j = 0; j < 8; j++) {
        float* cc = c[j];
        int col = j*8 + i2;
        *(uint32_t*)&g_Qh[r0*DH + col] = pk2bf(cc[0]*SCALE, cc[1]*SCALE);
        *(uint32_t*)&g_Qh[r1*DH + col] = pk2bf(cc[2]*SCALE, cc[3]*SCALE);
        float* ck = c[8 + j];
        *(uint32_t*)&g_Kh[r0*DH + col] = pk2bf(ck[0], ck[1]);
        *(uint32_t*)&g_Kh[r1*DH + col] = pk2bf(ck[2], ck[3]);
    }
    #pragma unroll
    for (int j = 0; j < 8; j++) {
        float* cc = c[16 + j];
        uint32_t h, l;
        int col = j*8 + i2;
        splitpk(cc[0], cc[1], h, l);
        *(uint32_t*)&g_Vh[r0*DH + col] = h;
        *(uint32_t*)&g_Vl[r0*DH + col] = l;
        splitpk(cc[2], cc[3], h, l);
        *(uint32_t*)&g_Vh[r1*DH + col] = h;
        *(uint32_t*)&g_Vl[r1*DH + col] = l;
    }
}

// ================= Kernel 2: flash attention via mma.sync (pipelined, occ 1) =================
// S = Qh*Kh.  All tiles mean-shifted: P = 1 + P' (masked entries -> P' = -1 exactly).
// Non-diag: O += colsum(V) + P'*Vh.   Diag: O += colsum(V) + P'*(Vh+Vl).
// Buffer: KH 16K | VH 16K | VL 16K | VSUM 256B pad 1K -> FB=50176; double-buffered.
#define FB 50176
#define FV_SUM 49152
#define FLASH_SMEM (2*FB)

__device__ __forceinline__ void flash_prefetch(uint32_t sb, int p, long krow, int tid, bool need_vl) {
    uint32_t base = sb + p*FB;
    for (int i = tid; i < 1024; i += 256) {
        int r = i >> 3, c8 = (i & 7) * 8;
        uint32_t o = SWZ((uint32_t)(r*128 + c8*2));
        long gi = (krow + r)*DH + c8;
        cp16(base + o,         &g_Kh[gi]);
        cp16(base + 16384 + o, &g_Vh[gi]);
        if (need_vl) cp16(base + 32768 + o, &g_Vl[gi]);
    }
    if (tid < 16) cp16(base + FV_SUM + tid*16, &g_Vsum[(krow >> 7)*64 + tid*4]);
}

__global__ void __launch_bounds__(256, 1) flash_kernel() {
    int cch = blockIdx.x;
    int qt = (QT - 1) - blockIdx.y;
    int b = blockIdx.z;
    int j0 = cch * CKT;
    if (j0 > qt) return;
    int nt = min(j0 + CKT, qt + 1) - j0;

    extern __shared__ char smem[];
    uint32_t sb = s2u(smem);
    int tid = threadIdx.x, lane = tid & 31, w = tid >> 5;
    int g = lane >> 2, i2 = (lane & 3) * 2;

    // stage Q (hi only) through buffer 1
    long qrow = (long)b*TT + (long)qt*128;
    for (int i = tid; i < 1024; i += 256) {
        int r = i >> 3, c8 = (i & 7) * 8;
        uint32_t o = SWZ((uint32_t)(r*128 + c8*2));
        *(uint4*)(smem + FB + o) = *(const uint4*)&g_Qh[(qrow + r)*DH + c8];
    }
    flash_prefetch(sb, 0, (long)b*TT + (long)j0*128, tid, j0 == qt);
    CPCOMMIT();
    __syncthreads();
    uint32_t qh[4][4];
    #pragma unroll
    for (int ks = 0; ks < 4; ks++) {
        int r = 16*w + (lane & 15);
        int cb = ks*32 + (lane >> 4) * 16;
        ldsm4(qh[ks][0], qh[ks][1], qh[ks][2], qh[ks][3], swaddr(sb + FB, r, cb));
    }

    float oacc[8][4];
    #pragma unroll
    for (int i = 0; i < 8; i++)
        #pragma unroll
        for (int k = 0; k < 4; k++) oacc[i][k] = 0.f;
    float li0 = 0.f, li1 = 0.f;
    int qr0 = 16*w + g, qr1 = qr0 + 8;

    for (int jj = 0; jj < nt; jj++) {
        int j = j0 + jj;
        bool diag = (j == qt);
        __syncthreads();
        if (jj + 1 < nt) {
            flash_prefetch(sb, (jj+1) & 1, (long)b*TT + (long)(j+1)*128, tid, (j+1) == qt);
            CPCOMMIT();
            CPWAIT(1);
        } else {
            CPWAIT(0);
        }
        __syncthreads();
        uint32_t bKH = sb + (jj & 1)*FB;
        uint32_t bVH = bKH + 16384;
        uint32_t bVL = bKH + 32768;

        // S = Qh Kh^T  (16 n-tiles of 8)
        float sacc[16][4];
        #pragma unroll
        for (int i = 0; i < 16; i++)
            #pragma unroll
            for (int k = 0; k < 4; k++) sacc[i][k] = 0.f;
        #pragma unroll
        for (int ks = 0; ks < 4; ks++) {
            #pragma unroll
            for (int j2 = 0; j2 < 8; j2++) {
                uint32_t bh[4];
                int r = j2*16 + ((lane >> 4) & 1)*8 + (lane & 7);
                int cb = ks*32 + ((lane >> 3) & 1)*16;
                ldsm4(bh[0], bh[1], bh[2], bh[3], swaddr(bKH, r, cb));
                mma16816(sacc[2*j2],     qh[ks], bh[0], bh[1]);
                mma16816(sacc[2*j2 + 1], qh[ks], bh[2], bh[3]);
            }
        }

        // exp + (diag) mask + pack P' = p - 1 (masked -> exactly -1)
        uint32_t pah[16][2];
        #pragma unroll
        for (int t = 0; t < 16; t++) {
            float p0 = __expf(sacc[t][0]);
            float p1 = __expf(sacc[t][1]);
            float p2 = __expf(sacc[t][2]);
            float p3 = __expf(sacc[t][3]);
            if (diag) {
                int col = 8*t + i2;
                if (col     > qr0) p0 = 0.f;
                if (col + 1 > qr0) p1 = 0.f;
                if (col     > qr1) p2 = 0.f;
                if (col + 1 > qr1) p3 = 0.f;
            }
            li0 += p0 + p1;
            li1 += p2 + p3;
            pah[t][0] = pk2bf(p0 - 1.0f, p1 - 1.0f);
            pah[t][1] = pk2bf(p2 - 1.0f, p3 - 1.0f);
        }

        // O += P' Vh  (+ P' Vl on diag: the -1 entries cancel colsum's V-lo mass)
        #pragma unroll
        for (int kk = 0; kk < 8; kk++) {
            uint32_t ah[4] = {pah[2*kk][0], pah[2*kk][1], pah[2*kk+1][0], pah[2*kk+1][1]};
            #pragma unroll
            for (int j2 = 0; j2 < 4; j2++) {
                uint32_t bh[4];
                int r = kk*16 + ((lane >> 3) & 1)*8 + (lane & 7);
                int cb = j2*32 + ((lane >> 4) & 1)*16;
                ldsm4t(bh[0], bh[1], bh[2], bh[3], swaddr(bVH, r, cb));
                mma16816(oacc[2*j2],     ah, bh[0], bh[1]);
                mma16816(oacc[2*j2 + 1], ah, bh[2], bh[3]);
                if (diag) {
                    uint32_t bl[4];
                    ldsm4t(bl[0], bl[1], bl[2], bl[3], swaddr(bVL, r, cb));
                    mma16816(oacc[2*j2],     ah, bl[0], bl[1]);
                    mma16816(oacc[2*j2 + 1], ah, bl[2], bl[3]);
                }
            }
        }
        // O += colsum(V)  (exact fp32 rank-1; full V incl. lo)
        {
            const float* vs = (const float*)(smem + (jj & 1)*FB + FV_SUM);
            #pragma unroll
            for (int jt = 0; jt < 8; jt++) {
                float2 v = *(const float2*)&vs[8*jt + i2];
                oacc[jt][0] += v.x; oacc[jt][1] += v.y;
                oacc[jt][2] += v.x; oacc[jt][3] += v.y;
            }
        }
    }

    // reduce row-sums across the quad
    li0 += __shfl_xor_sync(0xffffffffu, li0, 1);
    li0 += __shfl_xor_sync(0xffffffffu, li0, 2);
    li1 += __shfl_xor_sync(0xffffffffu, li1, 1);
    li1 += __shfl_xor_sync(0xffffffffu, li1, 2);

    // write partials
    long pidx = (long)(b*QT + qt)*NCHUNK + cch;
    #pragma unroll
    for (int jt = 0; jt < 8; jt++) {
        int col = 8*jt + i2;
        *(float2*)&g_Op[(pidx*128 + qr0)*DH + col] = make_float2(oacc[jt][0], oacc[jt][1]);
        *(float2*)&g_Op[(pidx*128 + qr1)*DH + col] = make_float2(oacc[jt][2], oacc[jt][3]);
    }
    if ((lane & 3) == 0) {
        g_lp[pidx*128 + qr0] = li0;
        g_lp[pidx*128 + qr1] = li1;
    }
}

// ================= Kernel 3: merge (parallelized) =================
__global__ void merge_kernel(float* __restrict__ out) {
    int qt = blockIdx.x >> 2, quar = blockIdx.x & 3;
    int b = blockIdx.y;
    int nc = qt / CKT + 1;
    long pbase = (long)(b*QT + qt)*NCHUNK;
    int r0 = quar * 32;
    __shared__ float invl[32];
    int tid = threadIdx.x;
    if (tid < 32) {
        float lt = 0.f;
        #pragma unroll
        for (int cc = 0; cc < NCHUNK; cc++)
            if (cc < nc) lt += g_lp[(pbase + cc)*128 + r0 + tid];
        invl[tid] = 1.0f / lt;
    }
    __syncthreads();
    for (int i = tid; i < 512; i += 256) {
        int m = i >> 4, c4 = (i & 15) * 4;
        float4 acc = make_float4(0.f, 0.f, 0.f, 0.f);
        #pragma unroll
        for (int cc = 0; cc < NCHUNK; cc++) {
            if (cc < nc) {
                float4 v = *(const float4*)&g_Op[((pbase + cc)*128 + r0 + m)*DH + c4];
                acc.x += v.x; acc.y += v.y; acc.z += v.z; acc.w += v.w;
            }
        }
        float s = invl[m];
        long o = ((long)b*TT + (long)qt*128 + r0 + m)*DH + c4;
        *(float4*)&out[o] = make_float4(acc.x*s, acc.y*s, acc.z*s, acc.w*s);
    }
}

// =================================================================================
extern "C" void kernel_launch(void* const* d_in, const int* in_sizes, int n_in,
                              void* d_out, int out_size) {
    const float* x  = (const float*)d_in[0];
    const float* Wq = (const float*)d_in[1];
    const float* Wk = (const float*)d_in[2];
    const float* Wv = (const float*)d_in[3];
    float* out = (float*)d_out;

    cudaFuncSetAttribute(proj_kernel,  cudaFuncAttributeMaxDynamicSharedMemorySize, PROJ_SMEM);
    cudaFuncSetAttribute(flash_kernel, cudaFuncAttributeMaxDynamicSharedMemorySize, FLASH_SMEM);

    wprep_kernel<<<24, 256>>>(Wq, Wk, Wv);
    proj_kernel<<<NROW/128, 256, PROJ_SMEM>>>(x);
    flash_kernel<<<dim3(NCHUNK, QT, BB), 256, FLASH_SMEM>>>();
    merge_kernel<<<dim3(QT*4, BB), 256>>>(out);
}

// round 16
// speedup vs baseline: 1.1075x; 1.1075x over previous
#include <cuda_runtime.h>
#include <cuda_bf16.h>
#include <stdint.h>

#define BB 4
#define TT 4096
#define DD 1024
#define DH 64
#define NROW (BB*TT)
#define QT 32
#define CKT 8
#define NCHUNK 4
#define SCALE 0.03125f

#define SWZ(o) ((o) ^ (((o) >> 3) & 0x70))

__device__ __forceinline__ uint32_t s2u(const void* p) {
    uint32_t a; asm("{ .reg .u64 t; cvta.to.shared.u64 t, %1; cvt.u32.u64 %0, t; }" : "=r"(a) : "l"(p)); return a;
}
__device__ __forceinline__ uint32_t swaddr(uint32_t base, int row, int cb) {
    uint32_t o = (uint32_t)(row * 128 + cb);
    return base + (o ^ ((o >> 3) & 0x70));
}
__device__ __forceinline__ void ldsm4(uint32_t& r0, uint32_t& r1, uint32_t& r2, uint32_t& r3, uint32_t a) {
    asm volatile("ldmatrix.sync.aligned.m8n8.x4.shared.b16 {%0,%1,%2,%3}, [%4];"
                 : "=r"(r0), "=r"(r1), "=r"(r2), "=r"(r3) : "r"(a));
}
__device__ __forceinline__ void ldsm4t(uint32_t& r0, uint32_t& r1, uint32_t& r2, uint32_t& r3, uint32_t a) {
    asm volatile("ldmatrix.sync.aligned.m8n8.x4.trans.shared.b16 {%0,%1,%2,%3}, [%4];"
                 : "=r"(r0), "=r"(r1), "=r"(r2), "=r"(r3) : "r"(a));
}
__device__ __forceinline__ void mma16816(float* c, const uint32_t* a, uint32_t b0, uint32_t b1) {
    asm volatile("mma.sync.aligned.m16n8k16.row.col.f32.bf16.bf16.f32 "
                 "{%0,%1,%2,%3}, {%4,%5,%6,%7}, {%8,%9}, {%0,%1,%2,%3};"
                 : "+f"(c[0]), "+f"(c[1]), "+f"(c[2]), "+f"(c[3])
                 : "r"(a[0]), "r"(a[1]), "r"(a[2]), "r"(a[3]), "r"(b0), "r"(b1));
}
// cp.async 16B (sm_80 baseline PTX; LDGSTS in SASS)
__device__ __forceinline__ void cp16(uint32_t dst, const void* src) {
    uint64_t g; asm("cvta.to.global.u64 %0, %1;" : "=l"(g) : "l"(src));
    asm volatile("cp.async.cg.shared.global [%0], [%1], 16;" :: "r"(dst), "l"(g));
}
#define CPCOMMIT() asm volatile("cp.async.commit_group;" ::: "memory")
#define CPWAIT(n)  asm volatile("cp.async.wait_group %0;" :: "n"(n) : "memory")

__device__ __forceinline__ void splitpk(float f0, float f1, uint32_t& h, uint32_t& l) {
    __nv_bfloat162 hb = __floats2bfloat162_rn(f0, f1);
    h = *(uint32_t*)&hb;
    float l0 = f0 - __bfloat162float(hb.x);
    float l1 = f1 - __bfloat162float(hb.y);
    __nv_bfloat162 lb = __floats2bfloat162_rn(l0, l1);
    l = *(uint32_t*)&lb;
}
__device__ __forceinline__ uint32_t pk2bf(float f0, float f1) {
    __nv_bfloat162 hb = __floats2bfloat162_rn(f0, f1);
    return *(uint32_t*)&hb;
}

// ---------------- device scratch ----------------
__device__ __nv_bfloat16 g_Wth[3*DH*DD];          // [mat][n][k]
__device__ __nv_bfloat16 g_Wtl[3*DH*DD];
__device__ __nv_bfloat16 g_Qh[(long)NROW*DH];     // Q: single bf16 (damped via S)
__device__ __nv_bfloat16 g_Kh[(long)NROW*DH];     // K: single bf16 (damped via S)
__device__ __nv_bfloat16 g_Vh[(long)NROW*DH], g_Vl[(long)NROW*DH];  // V: hi/lo (undamped)
__device__ float g_Vsum[(NROW/128)*64];           // per key tile: column sums of V (fp32)
__device__ float g_Op[(long)BB*QT*NCHUNK*128*DH];
__device__ float g_lp[BB*QT*NCHUNK*128];

// ================= Kernel 0: W transpose + hi/lo split =================
__global__ void wprep_kernel(const float* __restrict__ Wq,
                             const float* __restrict__ Wk,
                             const float* __restrict__ Wv) {
    __shared__ float Ws[128*65];
    int mat = blockIdx.x >> 3;
    int k0  = (blockIdx.x & 7) * 128;
    const float* W = (mat == 0) ? Wq : (mat == 1) ? Wk : Wv;
    int tid = threadIdx.x;
    for (int i = tid; i < 2048; i += 256) {
        int k = i >> 4, n4 = (i & 15) * 4;
        float4 w = *(const float4*)&W[(long)(k0 + k)*DH + n4];
        float* p = &Ws[k*65 + n4];
        p[0] = w.x; p[1] = w.y; p[2] = w.z; p[3] = w.w;
    }
    __syncthreads();
    for (int i = tid; i < 2048; i += 256) {
        int n = i >> 5, k4 = (i & 31) * 4;
        uint32_t h0, l0, h1, l1;
        splitpk(Ws[(k4+0)*65 + n], Ws[(k4+1)*65 + n], h0, l0);
        splitpk(Ws[(k4+2)*65 + n], Ws[(k4+3)*65 + n], h1, l1);
        long off = (long)mat*DH*DD + (long)n*DD + k0 + k4;
        *(uint2*)&g_Wth[off] = make_uint2(h0, h1);
        *(uint2*)&g_Wtl[off] = make_uint2(l0, l1);
    }
}

// ================= Kernel 1: QKV projection via mma.sync (pipelined) =================
// Terms: Q,K = Xh*Wh (1, damped via S);  V = Xh*Wh + Xh*Wl + Xl*Wh (3, undamped).
#define PB 81920
#define PJ_XS 0
#define PJ_WB 32768
#define PJ_XHs (2*PB)
#define PJ_XLs (2*PB + 16384)
#define PROJ_SMEM (2*PB + 32768)

__device__ __forceinline__ void proj_prefetch(uint32_t sb, char* smem, int p,
                                              const float* x, long rowbase, int k0, int tid) {
    uint32_t base = sb + p*PB;
    for (int i = tid; i < 2048; i += 256) {
        int r = i >> 4, c4 = (i & 15) * 4;
        cp16(base + PJ_XS + (uint32_t)(r*256 + c4*4), &x[(rowbase + r)*DD + k0 + c4]);
    }
    // W tiles needed: t in {0 (Q-hi), 2 (K-hi), 4 (V-hi), 5 (V-lo)}
    for (int i = tid; i < 2048; i += 256) {
        int tt = i >> 9, idx = i & 511;
        int t = (tt == 0) ? 0 : (tt == 1) ? 2 : tt + 2;
        int n = idx >> 3, k8 = (idx & 7) * 8;
        int mat = t >> 1, hl = t & 1;
        const __nv_bfloat16* src = (hl ? g_Wtl : g_Wth) + (long)mat*DH*DD;
        cp16(base + PJ_WB + t*8192 + SWZ((uint32_t)(n*128 + k8*2)), &src[(long)n*DD + k0 + k8]);
    }
}

__global__ void __launch_bounds__(256, 1) proj_kernel(const float* __restrict__ x) {
    extern __shared__ char smem[];
    uint32_t sb = s2u(smem);
    int tid = threadIdx.x, lane = tid & 31, w = tid >> 5;
    long rowbase = (long)blockIdx.x * 128;

    float c[24][4];
    #pragma unroll
    for (int i = 0; i < 24; i++)
        #pragma unroll
        for (int k = 0; k < 4; k++) c[i][k] = 0.f;

    proj_prefetch(sb, smem, 0, x, rowbase, 0, tid);
    CPCOMMIT();

    for (int kc = 0; kc < 16; kc++) {
        int p = kc & 1;
        __syncthreads();
        if (kc + 1 < 16) {
            proj_prefetch(sb, smem, (kc+1) & 1, x, rowbase, (kc+1)*64, tid);
            CPCOMMIT();
            CPWAIT(1);
        } else {
            CPWAIT(0);
        }
        __syncthreads();
        {
            const float* xs = (const float*)(smem + p*PB + PJ_XS);
            for (int i = tid; i < 2048; i += 256) {
                int r = i >> 4, c4 = (i & 15) * 4;
                float4 v = *(const float4*)&xs[r*64 + c4];
                uint32_t h0, l0, h1, l1;
                splitpk(v.x, v.y, h0, l0);
                splitpk(v.z, v.w, h1, l1);
                uint32_t o = SWZ((uint32_t)(r*128 + c4*2));
                *(uint2*)(smem + PJ_XHs + o) = make_uint2(h0, h1);
                *(uint2*)(smem + PJ_XLs + o) = make_uint2(l0, l1);
            }
        }
        __syncthreads();
        uint32_t wbase = sb + p*PB + PJ_WB;
        #pragma unroll
        for (int ks = 0; ks < 4; ks++) {
            uint32_t ah[4], al[4];
            {
                int r = 16*w + (lane & 15);
                int cb = ks*32 + (lane >> 4) * 16;
                ldsm4(ah[0], ah[1], ah[2], ah[3], swaddr(sb + PJ_XHs, r, cb));
                ldsm4(al[0], al[1], al[2], al[3], swaddr(sb + PJ_XLs, r, cb));
            }
            #pragma unroll
            for (int mat = 0; mat < 3; mat++) {
                uint32_t bhB = wbase + (mat*2+0)*8192;
                uint32_t blB = wbase + (mat*2+1)*8192;
                #pragma unroll
                for (int j2 = 0; j2 < 4; j2++) {
                    uint32_t bh[4];
                    int r = j2*16 + ((lane >> 4) & 1)*8 + (lane & 7);
                    int cb = ks*32 + ((lane >> 3) & 1)*16;
                    ldsm4(bh[0], bh[1], bh[2], bh[3], swaddr(bhB, r, cb));
                    float* c0 = c[mat*8 + 2*j2];
                    float* c1 = c[mat*8 + 2*j2 + 1];
                    mma16816(c0, ah, bh[0], bh[1]);
                    mma16816(c1, ah, bh[2], bh[3]);
                    if (mat == 2) {
                        uint32_t bl[4];
                        ldsm4(bl[0], bl[1], bl[2], bl[3], swaddr(blB, r, cb));
                        mma16816(c0, al, bh[0], bh[1]);
                        mma16816(c1, al, bh[2], bh[3]);
                        mma16816(c0, ah, bl[0], bl[1]);
                        mma16816(c1, ah, bl[2], bl[3]);
                    }
                }
            }
        }
    }

    int g = lane >> 2, i2 = (lane & 3) * 2;

    // ---- V column sums for this 128-row tile (rank-1 flash correction) ----
    __syncthreads();
    {
        float* vss = (float*)(smem + PJ_XHs);   // [8 warps][64]
        float s0[8], s1[8];
        #pragma unroll
        for (int jt = 0; jt < 8; jt++) {
            s0[jt] = c[16+jt][0] + c[16+jt][2];
            s1[jt] = c[16+jt][1] + c[16+jt][3];
        }
        #pragma unroll
        for (int off = 4; off < 32; off <<= 1) {
            #pragma unroll
            for (int jt = 0; jt < 8; jt++) {
                s0[jt] += __shfl_xor_sync(0xffffffffu, s0[jt], off);
                s1[jt] += __shfl_xor_sync(0xffffffffu, s1[jt], off);
            }
        }
        if (lane < 4) {
            #pragma unroll
            for (int jt = 0; jt < 8; jt++) {
                vss[w*64 + 8*jt + i2]     = s0[jt];
                vss[w*64 + 8*jt + i2 + 1] = s1[jt];
            }
        }
        __syncthreads();
        if (tid < 64) {
            float t = 0.f;
            #pragma unroll
            for (int ww = 0; ww < 8; ww++) t += vss[ww*64 + tid];
            g_Vsum[(rowbase >> 7)*64 + tid] = t;
        }
    }

    // write Q,K (single bf16; Q scaled) and V (hi/lo)
    long r0 = rowbase + 16*w + g;
    long r1 = r0 + 8;
    #pragma unroll
    for (int j = 0; j < 8; j++) {
        float* cc = c[j];
        int col = j*8 + i2;
        *(uint32_t*)&g_Qh[r0*DH + col] = pk2bf(cc[0]*SCALE, cc[1]*SCALE);
        *(uint32_t*)&g_Qh[r1*DH + col] = pk2bf(cc[2]*SCALE, cc[3]*SCALE);
        float* ck = c[8 + j];
        *(uint32_t*)&g_Kh[r0*DH + col] = pk2bf(ck[0], ck[1]);
        *(uint32_t*)&g_Kh[r1*DH + col] = pk2bf(ck[2], ck[3]);
    }
    #pragma unroll
    for (int j = 0; j < 8; j++) {
        float* cc = c[16 + j];
        uint32_t h, l;
        int col = j*8 + i2;
        splitpk(cc[0], cc[1], h, l);
        *(uint32_t*)&g_Vh[r0*DH + col] = h;
        *(uint32_t*)&g_Vl[r0*DH + col] = l;
        splitpk(cc[2], cc[3], h, l);
        *(uint32_t*)&g_Vh[r1*DH + col] = h;
        *(uint32_t*)&g_Vl[r1*DH + col] = l;
    }
}

// ================= Kernel 2: flash attention via mma.sync (pipelined) =================
// S = Qh*Kh.  Non-diag (straight-line): P = 1 + P' -> O += colsum(V) + P'*Vh.
// Diag (separate straight-line branch): mask p->0, P' = p-1 (-1 exact on masked),
//   O += colsum(V) + P'*(Vh+Vl).
// Buffer: KH 16K | VH 16K | VL 16K | VSUM 256B pad 1K -> FB=50176; double-buffered.
#define FB 50176
#define FV_SUM 49152
#define FLASH_SMEM (2*FB)

__device__ __forceinline__ void flash_prefetch(uint32_t sb, int p, long krow, int tid) {
    uint32_t base = sb + p*FB;
    for (int i = tid; i < 1024; i += 256) {
        int r = i >> 3, c8 = (i & 7) * 8;
        uint32_t o = SWZ((uint32_t)(r*128 + c8*2));
        long gi = (krow + r)*DH + c8;
        cp16(base + o,         &g_Kh[gi]);
        cp16(base + 16384 + o, &g_Vh[gi]);
        cp16(base + 32768 + o, &g_Vl[gi]);
    }
    if (tid < 16) cp16(base + FV_SUM + tid*16, &g_Vsum[(krow >> 7)*64 + tid*4]);
}

__global__ void __launch_bounds__(256, 1) flash_kernel() {
    int cch = blockIdx.x;
    int qt = (QT - 1) - blockIdx.y;
    int b = blockIdx.z;
    int j0 = cch * CKT;
    if (j0 > qt) return;
    int nt = min(j0 + CKT, qt + 1) - j0;

    extern __shared__ char smem[];
    uint32_t sb = s2u(smem);
    int tid = threadIdx.x, lane = tid & 31, w = tid >> 5;
    int g = lane >> 2, i2 = (lane & 3) * 2;

    // stage Q (hi only) through buffer 1
    long qrow = (long)b*TT + (long)qt*128;
    for (int i = tid; i < 1024; i += 256) {
        int r = i >> 3, c8 = (i & 7) * 8;
        uint32_t o = SWZ((uint32_t)(r*128 + c8*2));
        *(uint4*)(smem + FB + o) = *(const uint4*)&g_Qh[(qrow + r)*DH + c8];
    }
    flash_prefetch(sb, 0, (long)b*TT + (long)j0*128, tid);
    CPCOMMIT();
    __syncthreads();
    uint32_t qh[4][4];
    #pragma unroll
    for (int ks = 0; ks < 4; ks++) {
        int r = 16*w + (lane & 15);
        int cb = ks*32 + (lane >> 4) * 16;
        ldsm4(qh[ks][0], qh[ks][1], qh[ks][2], qh[ks][3], swaddr(sb + FB, r, cb));
    }

    float oacc[8][4];
    #pragma unroll
    for (int i = 0; i < 8; i++)
        #pragma unroll
        for (int k = 0; k < 4; k++) oacc[i][k] = 0.f;
    float li0 = 0.f, li1 = 0.f;
    int qr0 = 16*w + g, qr1 = qr0 + 8;

    for (int jj = 0; jj < nt; jj++) {
        int j = j0 + jj;
        __syncthreads();
        if (jj + 1 < nt) {
            flash_prefetch(sb, (jj+1) & 1, (long)b*TT + (long)(j+1)*128, tid);
            CPCOMMIT();
            CPWAIT(1);
        } else {
            CPWAIT(0);
        }
        __syncthreads();
        uint32_t bKH = sb + (jj & 1)*FB;
        uint32_t bVH = bKH + 16384;
        uint32_t bVL = bKH + 32768;

        // S = Qh Kh^T  (16 n-tiles of 8)
        float sacc[16][4];
        #pragma unroll
        for (int i = 0; i < 16; i++)
            #pragma unroll
            for (int k = 0; k < 4; k++) sacc[i][k] = 0.f;
        #pragma unroll
        for (int ks = 0; ks < 4; ks++) {
            #pragma unroll
            for (int j2 = 0; j2 < 8; j2++) {
                uint32_t bh[4];
                int r = j2*16 + ((lane >> 4) & 1)*8 + (lane & 7);
                int cb = ks*32 + ((lane >> 3) & 1)*16;
                ldsm4(bh[0], bh[1], bh[2], bh[3], swaddr(bKH, r, cb));
                mma16816(sacc[2*j2],     qh[ks], bh[0], bh[1]);
                mma16816(sacc[2*j2 + 1], qh[ks], bh[2], bh[3]);
            }
        }

        if (j != qt) {
            // ---- non-diag (straight-line, identical to R12's hot path) ----
            uint32_t pah[16][2];
            #pragma unroll
            for (int t = 0; t < 16; t++) {
                float p0 = __expf(sacc[t][0]);
                float p1 = __expf(sacc[t][1]);
                float p2 = __expf(sacc[t][2]);
                float p3 = __expf(sacc[t][3]);
                li0 += p0 + p1;
                li1 += p2 + p3;
                pah[t][0] = pk2bf(p0 - 1.0f, p1 - 1.0f);
                pah[t][1] = pk2bf(p2 - 1.0f, p3 - 1.0f);
            }
            #pragma unroll
            for (int kk = 0; kk < 8; kk++) {
                uint32_t ah[4] = {pah[2*kk][0], pah[2*kk][1], pah[2*kk+1][0], pah[2*kk+1][1]};
                #pragma unroll
                for (int j2 = 0; j2 < 4; j2++) {
                    uint32_t bh[4];
                    int r = kk*16 + ((lane >> 3) & 1)*8 + (lane & 7);
                    int cb = j2*32 + ((lane >> 4) & 1)*16;
                    ldsm4t(bh[0], bh[1], bh[2], bh[3], swaddr(bVH, r, cb));
                    mma16816(oacc[2*j2],     ah, bh[0], bh[1]);
                    mma16816(oacc[2*j2 + 1], ah, bh[2], bh[3]);
                }
            }
            {
                const float* vs = (const float*)(smem + (jj & 1)*FB + FV_SUM);
                #pragma unroll
                for (int jt = 0; jt < 8; jt++) {
                    float2 v = *(const float2*)&vs[8*jt + i2];
                    oacc[jt][0] += v.x; oacc[jt][1] += v.y;
                    oacc[jt][2] += v.x; oacc[jt][3] += v.y;
                }
            }
        } else {
            // ---- diag (separate straight-line branch): mean-shift + exact mask ----
            uint32_t pah[16][2];
            #pragma unroll
            for (int t = 0; t < 16; t++) {
                float p0 = __expf(sacc[t][0]);
                float p1 = __expf(sacc[t][1]);
                float p2 = __expf(sacc[t][2]);
                float p3 = __expf(sacc[t][3]);
                int col = 8*t + i2;
                if (col     > qr0) p0 = 0.f;
                if (col + 1 > qr0) p1 = 0.f;
                if (col     > qr1) p2 = 0.f;
                if (col + 1 > qr1) p3 = 0.f;
                li0 += p0 + p1;
                li1 += p2 + p3;
                pah[t][0] = pk2bf(p0 - 1.0f, p1 - 1.0f);   // masked -> exactly -1
                pah[t][1] = pk2bf(p2 - 1.0f, p3 - 1.0f);
            }
            #pragma unroll
            for (int kk = 0; kk < 8; kk++) {
                uint32_t ah[4] = {pah[2*kk][0], pah[2*kk][1], pah[2*kk+1][0], pah[2*kk+1][1]};
                #pragma unroll
                for (int j2 = 0; j2 < 4; j2++) {
                    uint32_t bh[4], bl[4];
                    int r = kk*16 + ((lane >> 3) & 1)*8 + (lane & 7);
                    int cb = j2*32 + ((lane >> 4) & 1)*16;
                    ldsm4t(bh[0], bh[1], bh[2], bh[3], swaddr(bVH, r, cb));
                    ldsm4t(bl[0], bl[1], bl[2], bl[3], swaddr(bVL, r, cb));
                    mma16816(oacc[2*j2],     ah, bh[0], bh[1]);
                    mma16816(oacc[2*j2],     ah, bl[0], bl[1]);
                    mma16816(oacc[2*j2 + 1], ah, bh[2], bh[3]);
                    mma16816(oacc[2*j2 + 1], ah, bl[2], bl[3]);
                }
            }
            {
                const float* vs = (const float*)(smem + (jj & 1)*FB + FV_SUM);
                #pragma unroll
                for (int jt = 0; jt < 8; jt++) {
                    float2 v = *(const float2*)&vs[8*jt + i2];
                    oacc[jt][0] += v.x; oacc[jt][1] += v.y;
                    oacc[jt][2] += v.x; oacc[jt][3] += v.y;
                }
            }
        }
    }

    // reduce row-sums across the quad
    li0 += __shfl_xor_sync(0xffffffffu, li0, 1);
    li0 += __shfl_xor_sync(0xffffffffu, li0, 2);
    li1 += __shfl_xor_sync(0xffffffffu, li1, 1);
    li1 += __shfl_xor_sync(0xffffffffu, li1, 2);

    // write partials
    long pidx = (long)(b*QT + qt)*NCHUNK + cch;
    #pragma unroll
    for (int jt = 0; jt < 8; jt++) {
        int col = 8*jt + i2;
        *(float2*)&g_Op[(pidx*128 + qr0)*DH + col] = make_float2(oacc[jt][0], oacc[jt][1]);
        *(float2*)&g_Op[(pidx*128 + qr1)*DH + col] = make_float2(oacc[jt][2], oacc[jt][3]);
    }
    if ((lane & 3) == 0) {
        g_lp[pidx*128 + qr0] = li0;
        g_lp[pidx*128 + qr1] = li1;
    }
}

// ================= Kernel 3: merge (parallelized) =================
__global__ void merge_kernel(float* __restrict__ out) {
    int qt = blockIdx.x >> 2, quar = blockIdx.x & 3;
    int b = blockIdx.y;
    int nc = qt / CKT + 1;
    long pbase = (long)(b*QT + qt)*NCHUNK;
    int r0 = quar * 32;
    __shared__ float invl[32];
    int tid = threadIdx.x;
    if (tid < 32) {
        float lt = 0.f;
        #pragma unroll
        for (int cc = 0; cc < NCHUNK; cc++)
            if (cc < nc) lt += g_lp[(pbase + cc)*128 + r0 + tid];
        invl[tid] = 1.0f / lt;
    }
    __syncthreads();
    for (int i = tid; i < 512; i += 256) {
        int m = i >> 4, c4 = (i & 15) * 4;
        float4 acc = make_float4(0.f, 0.f, 0.f, 0.f);
        #pragma unroll
        for (int cc = 0; cc < NCHUNK; cc++) {
            if (cc < nc) {
                float4 v = *(const float4*)&g_Op[((pbase + cc)*128 + r0 + m)*DH + c4];
                acc.x += v.x; acc.y += v.y; acc.z += v.z; acc.w += v.w;
            }
        }
        float s = invl[m];
        long o = ((long)b*TT + (long)qt*128 + r0 + m)*DH + c4;
        *(float4*)&out[o] = make_float4(acc.x*s, acc.y*s, acc.z*s, acc.w*s);
    }
}

// =================================================================================
extern "C" void kernel_launch(void* const* d_in, const int* in_sizes, int n_in,
                              void* d_out, int out_size) {
    const float* x  = (const float*)d_in[0];
    const float* Wq = (const float*)d_in[1];
    const float* Wk = (const float*)d_in[2];
    const float* Wv = (const float*)d_in[3];
    float* out = (float*)d_out;

    cudaFuncSetAttribute(proj_kernel,  cudaFuncAttributeMaxDynamicSharedMemorySize, PROJ_SMEM);
    cudaFuncSetAttribute(flash_kernel, cudaFuncAttributeMaxDynamicSharedMemorySize, FLASH_SMEM);

    wprep_kernel<<<24, 256>>>(Wq, Wk, Wv);
    proj_kernel<<<NROW/128, 256, PROJ_SMEM>>>(x);
    flash_kernel<<<dim3(NCHUNK, QT, BB), 256, FLASH_SMEM>>>();
    merge_kernel<<<dim3(QT*4, BB), 256>>>(out);
}

// round 17
// speedup vs baseline: 1.1409x; 1.0302x over previous
#include <cuda_runtime.h>
#include <cuda_bf16.h>
#include <stdint.h>

#define BB 4
#define TT 4096
#define DD 1024
#define DH 64
#define NROW (BB*TT)
#define QT 32
#define CKT 8
#define NCHUNK 4
#define SCALE 0.03125f

#define SWZ(o) ((o) ^ (((o) >> 3) & 0x70))

__device__ __forceinline__ uint32_t s2u(const void* p) {
    uint32_t a; asm("{ .reg .u64 t; cvta.to.shared.u64 t, %1; cvt.u32.u64 %0, t; }" : "=r"(a) : "l"(p)); return a;
}
__device__ __forceinline__ uint32_t swaddr(uint32_t base, int row, int cb) {
    uint32_t o = (uint32_t)(row * 128 + cb);
    return base + (o ^ ((o >> 3) & 0x70));
}
__device__ __forceinline__ void ldsm4(uint32_t& r0, uint32_t& r1, uint32_t& r2, uint32_t& r3, uint32_t a) {
    asm volatile("ldmatrix.sync.aligned.m8n8.x4.shared.b16 {%0,%1,%2,%3}, [%4];"
                 : "=r"(r0), "=r"(r1), "=r"(r2), "=r"(r3) : "r"(a));
}
__device__ __forceinline__ void ldsm4t(uint32_t& r0, uint32_t& r1, uint32_t& r2, uint32_t& r3, uint32_t a) {
    asm volatile("ldmatrix.sync.aligned.m8n8.x4.trans.shared.b16 {%0,%1,%2,%3}, [%4];"
                 : "=r"(r0), "=r"(r1), "=r"(r2), "=r"(r3) : "r"(a));
}
__device__ __forceinline__ void mma16816(float* c, const uint32_t* a, uint32_t b0, uint32_t b1) {
    asm volatile("mma.sync.aligned.m16n8k16.row.col.f32.bf16.bf16.f32 "
                 "{%0,%1,%2,%3}, {%4,%5,%6,%7}, {%8,%9}, {%0,%1,%2,%3};"
                 : "+f"(c[0]), "+f"(c[1]), "+f"(c[2]), "+f"(c[3])
                 : "r"(a[0]), "r"(a[1]), "r"(a[2]), "r"(a[3]), "r"(b0), "r"(b1));
}
// cp.async 16B (sm_80 baseline PTX; LDGSTS in SASS)
__device__ __forceinline__ void cp16(uint32_t dst, const void* src) {
    uint64_t g; asm("cvta.to.global.u64 %0, %1;" : "=l"(g) : "l"(src));
    asm volatile("cp.async.cg.shared.global [%0], [%1], 16;" :: "r"(dst), "l"(g));
}
#define CPCOMMIT() asm volatile("cp.async.commit_group;" ::: "memory")
#define CPWAIT(n)  asm volatile("cp.async.wait_group %0;" :: "n"(n) : "memory")

__device__ __forceinline__ void splitpk(float f0, float f1, uint32_t& h, uint32_t& l) {
    __nv_bfloat162 hb = __floats2bfloat162_rn(f0, f1);
    h = *(uint32_t*)&hb;
    float l0 = f0 - __bfloat162float(hb.x);
    float l1 = f1 - __bfloat162float(hb.y);
    __nv_bfloat162 lb = __floats2bfloat162_rn(l0, l1);
    l = *(uint32_t*)&lb;
}
__device__ __forceinline__ uint32_t pk2bf(float f0, float f1) {
    __nv_bfloat162 hb = __floats2bfloat162_rn(f0, f1);
    return *(uint32_t*)&hb;
}

// ---------------- device scratch ----------------
__device__ __nv_bfloat16 g_Wth[3*DH*DD];          // [mat][n][k]
__device__ __nv_bfloat16 g_Wtl[3*DH*DD];
__device__ __nv_bfloat16 g_Qh[(long)NROW*DH];     // Q: single bf16 (damped via S)
__device__ __nv_bfloat16 g_Kh[(long)NROW*DH];     // K: single bf16 (damped via S)
__device__ __nv_bfloat16 g_Vh[(long)NROW*DH], g_Vl[(long)NROW*DH];  // V: hi/lo (undamped)
__device__ float g_Vsum[(NROW/128)*64];           // per key tile: column sums of V (fp32)
__device__ float g_Op[(long)BB*QT*NCHUNK*128*DH];
__device__ float g_lp[BB*QT*NCHUNK*128];

// ================= Kernel 0: W transpose + hi/lo split (96 blocks) =================
// Block = (mat, 32-wide k chunk).  Ws: [32 k][65] f32.
__global__ void wprep_kernel(const float* __restrict__ Wq,
                             const float* __restrict__ Wk,
                             const float* __restrict__ Wv) {
    __shared__ float Ws[32*65];
    int mat = blockIdx.x >> 5;
    int k0  = (blockIdx.x & 31) * 32;
    const float* W = (mat == 0) ? Wq : (mat == 1) ? Wk : Wv;
    int tid = threadIdx.x;
    for (int i = tid; i < 512; i += 256) {
        int k = i >> 4, n4 = (i & 15) * 4;
        float4 w = *(const float4*)&W[(long)(k0 + k)*DH + n4];
        float* p = &Ws[k*65 + n4];
        p[0] = w.x; p[1] = w.y; p[2] = w.z; p[3] = w.w;
    }
    __syncthreads();
    for (int i = tid; i < 512; i += 256) {
        int n = i >> 3, k4 = (i & 7) * 4;
        uint32_t h0, l0, h1, l1;
        splitpk(Ws[(k4+0)*65 + n], Ws[(k4+1)*65 + n], h0, l0);
        splitpk(Ws[(k4+2)*65 + n], Ws[(k4+3)*65 + n], h1, l1);
        long off = (long)mat*DH*DD + (long)n*DD + k0 + k4;
        *(uint2*)&g_Wth[off] = make_uint2(h0, h1);
        *(uint2*)&g_Wtl[off] = make_uint2(l0, l1);
    }
}

// ================= Kernel 1: QKV projection via mma.sync (pipelined) =================
// Terms: Q,K = Xh*Wh (1, damped via S);  V = Xh*Wh + Xh*Wl + Xl*Wh (3, undamped).
#define PB 81920
#define PJ_XS 0
#define PJ_WB 32768
#define PJ_XHs (2*PB)
#define PJ_XLs (2*PB + 16384)
#define PROJ_SMEM (2*PB + 32768)

__device__ __forceinline__ void proj_prefetch(uint32_t sb, char* smem, int p,
                                              const float* x, long rowbase, int k0, int tid) {
    uint32_t base = sb + p*PB;
    for (int i = tid; i < 2048; i += 256) {
        int r = i >> 4, c4 = (i & 15) * 4;
        cp16(base + PJ_XS + (uint32_t)(r*256 + c4*4), &x[(rowbase + r)*DD + k0 + c4]);
    }
    // W tiles needed: t in {0 (Q-hi), 2 (K-hi), 4 (V-hi), 5 (V-lo)}
    for (int i = tid; i < 2048; i += 256) {
        int tt = i >> 9, idx = i & 511;
        int t = (tt == 0) ? 0 : (tt == 1) ? 2 : tt + 2;
        int n = idx >> 3, k8 = (idx & 7) * 8;
        int mat = t >> 1, hl = t & 1;
        const __nv_bfloat16* src = (hl ? g_Wtl : g_Wth) + (long)mat*DH*DD;
        cp16(base + PJ_WB + t*8192 + SWZ((uint32_t)(n*128 + k8*2)), &src[(long)n*DD + k0 + k8]);
    }
}

__global__ void __launch_bounds__(256, 1) proj_kernel(const float* __restrict__ x) {
    extern __shared__ char smem[];
    uint32_t sb = s2u(smem);
    int tid = threadIdx.x, lane = tid & 31, w = tid >> 5;
    long rowbase = (long)blockIdx.x * 128;

    float c[24][4];
    #pragma unroll
    for (int i = 0; i < 24; i++)
        #pragma unroll
        for (int k = 0; k < 4; k++) c[i][k] = 0.f;

    proj_prefetch(sb, smem, 0, x, rowbase, 0, tid);
    CPCOMMIT();

    for (int kc = 0; kc < 16; kc++) {
        int p = kc & 1;
        __syncthreads();
        if (kc + 1 < 16) {
            proj_prefetch(sb, smem, (kc+1) & 1, x, rowbase, (kc+1)*64, tid);
            CPCOMMIT();
            CPWAIT(1);
        } else {
            CPWAIT(0);
        }
        __syncthreads();
        {
            const float* xs = (const float*)(smem + p*PB + PJ_XS);
            for (int i = tid; i < 2048; i += 256) {
                int r = i >> 4, c4 = (i & 15) * 4;
                float4 v = *(const float4*)&xs[r*64 + c4];
                uint32_t h0, l0, h1, l1;
                splitpk(v.x, v.y, h0, l0);
                splitpk(v.z, v.w, h1, l1);
                uint32_t o = SWZ((uint32_t)(r*128 + c4*2));
                *(uint2*)(smem + PJ_XHs + o) = make_uint2(h0, h1);
                *(uint2*)(smem + PJ_XLs + o) = make_uint2(l0, l1);
            }
        }
        __syncthreads();
        uint32_t wbase = sb + p*PB + PJ_WB;
        #pragma unroll
        for (int ks = 0; ks < 4; ks++) {
            uint32_t ah[4], al[4];
            {
                int r = 16*w + (lane & 15);
                int cb = ks*32 + (lane >> 4) * 16;
                ldsm4(ah[0], ah[1], ah[2], ah[3], swaddr(sb + PJ_XHs, r, cb));
                ldsm4(al[0], al[1], al[2], al[3], swaddr(sb + PJ_XLs, r, cb));
            }
            #pragma unroll
            for (int mat = 0; mat < 3; mat++) {
                uint32_t bhB = wbase + (mat*2+0)*8192;
                uint32_t blB = wbase + (mat*2+1)*8192;
                #pragma unroll
                for (int j2 = 0; j2 < 4; j2++) {
                    uint32_t bh[4];
                    int r = j2*16 + ((lane >> 4) & 1)*8 + (lane & 7);
                    int cb = ks*32 + ((lane >> 3) & 1)*16;
                    ldsm4(bh[0], bh[1], bh[2], bh[3], swaddr(bhB, r, cb));
                    float* c0 = c[mat*8 + 2*j2];
                    float* c1 = c[mat*8 + 2*j2 + 1];
                    mma16816(c0, ah, bh[0], bh[1]);
                    mma16816(c1, ah, bh[2], bh[3]);
                    if (mat == 2) {
                        uint32_t bl[4];
                        ldsm4(bl[0], bl[1], bl[2], bl[3], swaddr(blB, r, cb));
                        mma16816(c0, al, bh[0], bh[1]);
                        mma16816(c1, al, bh[2], bh[3]);
                        mma16816(c0, ah, bl[0], bl[1]);
                        mma16816(c1, ah, bl[2], bl[3]);
                    }
                }
            }
        }
    }

    int g = lane >> 2, i2 = (lane & 3) * 2;

    // ---- V column sums for this 128-row tile (rank-1 flash correction) ----
    __syncthreads();
    {
        float* vss = (float*)(smem + PJ_XHs);   // [8 warps][64]
        float s0[8], s1[8];
        #pragma unroll
        for (int jt = 0; jt < 8; jt++) {
            s0[jt] = c[16+jt][0] + c[16+jt][2];
            s1[jt] = c[16+jt][1] + c[16+jt][3];
        }
        #pragma unroll
        for (int off = 4; off < 32; off <<= 1) {
            #pragma unroll
            for (int jt = 0; jt < 8; jt++) {
                s0[jt] += __shfl_xor_sync(0xffffffffu, s0[jt], off);
                s1[jt] += __shfl_xor_sync(0xffffffffu, s1[jt], off);
            }
        }
        if (lane < 4) {
            #pragma unroll
            for (int jt = 0; jt < 8; jt++) {
                vss[w*64 + 8*jt + i2]     = s0[jt];
                vss[w*64 + 8*jt + i2 + 1] = s1[jt];
            }
        }
        __syncthreads();
        if (tid < 64) {
            float t = 0.f;
            #pragma unroll
            for (int ww = 0; ww < 8; ww++) t += vss[ww*64 + tid];
            g_Vsum[(rowbase >> 7)*64 + tid] = t;
        }
    }

    // write Q,K (single bf16; Q scaled) and V (hi/lo)
    long r0 = rowbase + 16*w + g;
    long r1 = r0 + 8;
    #pragma unroll
    for (int j = 0; j < 8; j++) {
        float* cc = c[j];
        int col = j*8 + i2;
        *(uint32_t*)&g_Qh[r0*DH + col] = pk2bf(cc[0]*SCALE, cc[1]*SCALE);
        *(uint32_t*)&g_Qh[r1*DH + col] = pk2bf(cc[2]*SCALE, cc[3]*SCALE);
        float* ck = c[8 + j];
        *(uint32_t*)&g_Kh[r0*DH + col] = pk2bf(ck[0], ck[1]);
        *(uint32_t*)&g_Kh[r1*DH + col] = pk2bf(ck[2], ck[3]);
    }
    #pragma unroll
    for (int j = 0; j < 8; j++) {
        float* cc = c[16 + j];
        uint32_t h, l;
        int col = j*8 + i2;
        splitpk(cc[0], cc[1], h, l);
        *(uint32_t*)&g_Vh[r0*DH + col] = h;
        *(uint32_t*)&g_Vl[r0*DH + col] = l;
        splitpk(cc[2], cc[3], h, l);
        *(uint32_t*)&g_Vh[r1*DH + col] = h;
        *(uint32_t*)&g_Vl[r1*DH + col] = l;
    }
}

// ================= Kernel 2: flash attention via mma.sync (pipelined) =================
// S = Qh*Kh.  Non-diag (straight-line): P = 1 + P' -> O += colsum(V) + P'*Vh.
// Diag (separate straight-line branch): mask p->0, P' = p-1 (-1 exact on masked),
//   O += colsum(V) + P'*(Vh+Vl).
// Buffer: KH 16K | VH 16K | VL 16K | VSUM 256B pad 1K -> FB=50176; double-buffered.
#define FB 50176
#define FV_SUM 49152
#define FLASH_SMEM (2*FB)

__device__ __forceinline__ void flash_prefetch(uint32_t sb, int p, long krow, int tid) {
    uint32_t base = sb + p*FB;
    for (int i = tid; i < 1024; i += 256) {
        int r = i >> 3, c8 = (i & 7) * 8;
        uint32_t o = SWZ((uint32_t)(r*128 + c8*2));
        long gi = (krow + r)*DH + c8;
        cp16(base + o,         &g_Kh[gi]);
        cp16(base + 16384 + o, &g_Vh[gi]);
        cp16(base + 32768 + o, &g_Vl[gi]);
    }
    if (tid < 16) cp16(base + FV_SUM + tid*16, &g_Vsum[(krow >> 7)*64 + tid*4]);
}

__global__ void __launch_bounds__(256, 1) flash_kernel() {
    int cch = blockIdx.x;
    int qt = (QT - 1) - blockIdx.y;
    int b = blockIdx.z;
    int j0 = cch * CKT;
    if (j0 > qt) return;
    int nt = min(j0 + CKT, qt + 1) - j0;

    extern __shared__ char smem[];
    uint32_t sb = s2u(smem);
    int tid = threadIdx.x, lane = tid & 31, w = tid >> 5;
    int g = lane >> 2, i2 = (lane & 3) * 2;

    // stage Q (hi only) through buffer 1
    long qrow = (long)b*TT + (long)qt*128;
    for (int i = tid; i < 1024; i += 256) {
        int r = i >> 3, c8 = (i & 7) * 8;
        uint32_t o = SWZ((uint32_t)(r*128 + c8*2));
        *(uint4*)(smem + FB + o) = *(const uint4*)&g_Qh[(qrow + r)*DH + c8];
    }
    flash_prefetch(sb, 0, (long)b*TT + (long)j0*128, tid);
    CPCOMMIT();
    __syncthreads();
    uint32_t qh[4][4];
    #pragma unroll
    for (int ks = 0; ks < 4; ks++) {
        int r = 16*w + (lane & 15);
        int cb = ks*32 + (lane >> 4) * 16;
        ldsm4(qh[ks][0], qh[ks][1], qh[ks][2], qh[ks][3], swaddr(sb + FB, r, cb));
    }

    float oacc[8][4];
    #pragma unroll
    for (int i = 0; i < 8; i++)
        #pragma unroll
        for (int k = 0; k < 4; k++) oacc[i][k] = 0.f;
    float li0 = 0.f, li1 = 0.f;
    int qr0 = 16*w + g, qr1 = qr0 + 8;

    for (int jj = 0; jj < nt; jj++) {
        int j = j0 + jj;
        __syncthreads();
        if (jj + 1 < nt) {
            flash_prefetch(sb, (jj+1) & 1, (long)b*TT + (long)(j+1)*128, tid);
            CPCOMMIT();
            CPWAIT(1);
        } else {
            CPWAIT(0);
        }
        __syncthreads();
        uint32_t bKH = sb + (jj & 1)*FB;
        uint32_t bVH = bKH + 16384;
        uint32_t bVL = bKH + 32768;

        // S = Qh Kh^T  (16 n-tiles of 8)
        float sacc[16][4];
        #pragma unroll
        for (int i = 0; i < 16; i++)
            #pragma unroll
            for (int k = 0; k < 4; k++) sacc[i][k] = 0.f;
        #pragma unroll
        for (int ks = 0; ks < 4; ks++) {
            #pragma unroll
            for (int j2 = 0; j2 < 8; j2++) {
                uint32_t bh[4];
                int r = j2*16 + ((lane >> 4) & 1)*8 + (lane & 7);
                int cb = ks*32 + ((lane >> 3) & 1)*16;
                ldsm4(bh[0], bh[1], bh[2], bh[3], swaddr(bKH, r, cb));
                mma16816(sacc[2*j2],     qh[ks], bh[0], bh[1]);
                mma16816(sacc[2*j2 + 1], qh[ks], bh[2], bh[3]);
            }
        }

        if (j != qt) {
            // ---- non-diag (straight-line) ----
            uint32_t pah[16][2];
            #pragma unroll
            for (int t = 0; t < 16; t++) {
                float p0 = __expf(sacc[t][0]);
                float p1 = __expf(sacc[t][1]);
                float p2 = __expf(sacc[t][2]);
                float p3 = __expf(sacc[t][3]);
                li0 += p0 + p1;
                li1 += p2 + p3;
                pah[t][0] = pk2bf(p0 - 1.0f, p1 - 1.0f);
                pah[t][1] = pk2bf(p2 - 1.0f, p3 - 1.0f);
            }
            #pragma unroll
            for (int kk = 0; kk < 8; kk++) {
                uint32_t ah[4] = {pah[2*kk][0], pah[2*kk][1], pah[2*kk+1][0], pah[2*kk+1][1]};
                #pragma unroll
                for (int j2 = 0; j2 < 4; j2++) {
                    uint32_t bh[4];
                    int r = kk*16 + ((lane >> 3) & 1)*8 + (lane & 7);
                    int cb = j2*32 + ((lane >> 4) & 1)*16;
                    ldsm4t(bh[0], bh[1], bh[2], bh[3], swaddr(bVH, r, cb));
                    mma16816(oacc[2*j2],     ah, bh[0], bh[1]);
                    mma16816(oacc[2*j2 + 1], ah, bh[2], bh[3]);
                }
            }
            {
                const float* vs = (const float*)(smem + (jj & 1)*FB + FV_SUM);
                #pragma unroll
                for (int jt = 0; jt < 8; jt++) {
                    float2 v = *(const float2*)&vs[8*jt + i2];
                    oacc[jt][0] += v.x; oacc[jt][1] += v.y;
                    oacc[jt][2] += v.x; oacc[jt][3] += v.y;
                }
            }
        } else {
            // ---- diag (separate straight-line branch): mean-shift + exact mask ----
            uint32_t pah[16][2];
            #pragma unroll
            for (int t = 0; t < 16; t++) {
                float p0 = __expf(sacc[t][0]);
                float p1 = __expf(sacc[t][1]);
                float p2 = __expf(sacc[t][2]);
                float p3 = __expf(sacc[t][3]);
                int col = 8*t + i2;
                if (col     > qr0) p0 = 0.f;
                if (col + 1 > qr0) p1 = 0.f;
                if (col     > qr1) p2 = 0.f;
                if (col + 1 > qr1) p3 = 0.f;
                li0 += p0 + p1;
                li1 += p2 + p3;
                pah[t][0] = pk2bf(p0 - 1.0f, p1 - 1.0f);   // masked -> exactly -1
                pah[t][1] = pk2bf(p2 - 1.0f, p3 - 1.0f);
            }
            #pragma unroll
            for (int kk = 0; kk < 8; kk++) {
                uint32_t ah[4] = {pah[2*kk][0], pah[2*kk][1], pah[2*kk+1][0], pah[2*kk+1][1]};
                #pragma unroll
                for (int j2 = 0; j2 < 4; j2++) {
                    uint32_t bh[4], bl[4];
                    int r = kk*16 + ((lane >> 3) & 1)*8 + (lane & 7);
                    int cb = j2*32 + ((lane >> 4) & 1)*16;
                    ldsm4t(bh[0], bh[1], bh[2], bh[3], swaddr(bVH, r, cb));
                    ldsm4t(bl[0], bl[1], bl[2], bl[3], swaddr(bVL, r, cb));
                    mma16816(oacc[2*j2],     ah, bh[0], bh[1]);
                    mma16816(oacc[2*j2],     ah, bl[0], bl[1]);
                    mma16816(oacc[2*j2 + 1], ah, bh[2], bh[3]);
                    mma16816(oacc[2*j2 + 1], ah, bl[2], bl[3]);
                }
            }
            {
                const float* vs = (const float*)(smem + (jj & 1)*FB + FV_SUM);
                #pragma unroll
                for (int jt = 0; jt < 8; jt++) {
                    float2 v = *(const float2*)&vs[8*jt + i2];
                    oacc[jt][0] += v.x; oacc[jt][1] += v.y;
                    oacc[jt][2] += v.x; oacc[jt][3] += v.y;
                }
            }
        }
    }

    // reduce row-sums across the quad
    li0 += __shfl_xor_sync(0xffffffffu, li0, 1);
    li0 += __shfl_xor_sync(0xffffffffu, li0, 2);
    li1 += __shfl_xor_sync(0xffffffffu, li1, 1);
    li1 += __shfl_xor_sync(0xffffffffu, li1, 2);

    // write partials
    long pidx = (long)(b*QT + qt)*NCHUNK + cch;
    #pragma unroll
    for (int jt = 0; jt < 8; jt++) {
        int col = 8*jt + i2;
        *(float2*)&g_Op[(pidx*128 + qr0)*DH + col] = make_float2(oacc[jt][0], oacc[jt][1]);
        *(float2*)&g_Op[(pidx*128 + qr1)*DH + col] = make_float2(oacc[jt][2], oacc[jt][3]);
    }
    if ((lane & 3) == 0) {
        g_lp[pidx*128 + qr0] = li0;
        g_lp[pidx*128 + qr1] = li1;
    }
}

// ================= Kernel 3: merge (1024 blocks of 16 rows) =================
__global__ void merge_kernel(float* __restrict__ out) {
    int qt = blockIdx.x >> 3, oct = blockIdx.x & 7;
    int b = blockIdx.y;
    int nc = qt / CKT + 1;
    long pbase = (long)(b*QT + qt)*NCHUNK;
    int r0 = oct * 16;
    __shared__ float invl[16];
    int tid = threadIdx.x;
    if (tid < 16) {
        float lt = 0.f;
        #pragma unroll
        for (int cc = 0; cc < NCHUNK; cc++)
            if (cc < nc) lt += g_lp[(pbase + cc)*128 + r0 + tid];
        invl[tid] = 1.0f / lt;
    }
    __syncthreads();
    // 16 rows x 64 cols = 256 float4; 256 threads -> 1 each
    {
        int i = tid;
        int m = i >> 4, c4 = (i & 15) * 4;
        float4 acc = make_float4(0.f, 0.f, 0.f, 0.f);
        #pragma unroll
        for (int cc = 0; cc < NCHUNK; cc++) {
            if (cc < nc) {
                float4 v = *(const float4*)&g_Op[((pbase + cc)*128 + r0 + m)*DH + c4];
                acc.x += v.x; acc.y += v.y; acc.z += v.z; acc.w += v.w;
            }
        }
        float s = invl[m];
        long o = ((long)b*TT + (long)qt*128 + r0 + m)*DH + c4;
        *(float4*)&out[o] = make_float4(acc.x*s, acc.y*s, acc.z*s, acc.w*s);
    }
}

// =================================================================================
extern "C" void kernel_launch(void* const* d_in, const int* in_sizes, int n_in,
                              void* d_out, int out_size) {
    const float* x  = (const float*)d_in[0];
    const float* Wq = (const float*)d_in[1];
    const float* Wk = (const float*)d_in[2];
    const float* Wv = (const float*)d_in[3];
    float* out = (float*)d_out;

    cudaFuncSetAttribute(proj_kernel,  cudaFuncAttributeMaxDynamicSharedMemorySize, PROJ_SMEM);
    cudaFuncSetAttribute(flash_kernel, cudaFuncAttributeMaxDynamicSharedMemorySize, FLASH_SMEM);

    wprep_kernel<<<96, 256>>>(Wq, Wk, Wv);
    proj_kernel<<<NROW/128, 256, PROJ_SMEM>>>(x);
    flash_kernel<<<dim3(NCHUNK, QT, BB), 256, FLASH_SMEM>>>();
    merge_kernel<<<dim3(QT*8, BB), 256>>>(out);
}